// round 9
// baseline (speedup 1.0000x reference)
#include <cuda_runtime.h>

// Problem constants (shapes fixed by setup_inputs)
#define RESV 128
#define RES3 (RESV * RESV * RESV)     // 2,097,152
#define BB   4
#define CC   16
#define HH   256
#define WW   256
#define HW   (HH * WW)                // 65,536 pixels per batch
#define FHW  (32 * 32)                // feature spatial size

#define RB        32                  // reduction blocks (8 per batch)
#define SEG_PIX   (HW / 8)            // 8192 pixels per reduction block
#define ZB        8192                // zeroing blocks
#define F4_PER_BLK 4096               // float4s zeroed per block (64 KiB)

// Per-reduction-block partial mins (plain stores -> no init kernel needed).
__device__ float g_part[RB * 3];

// pc = (nocs + translation) * scale with exact rn add-then-mul; intrinsics
// are never FMA-contracted, so this is bit-identical to the reference's
// discrete add -> mul and identical between the reduce and scatter paths.
__device__ __forceinline__ float pc_axis(float n, float t, float s) {
    return __fmul_rn(__fadd_rn(n, t), s);
}

__device__ __forceinline__ bool valid_px(float m, float n0, float n1, float n2) {
    float sg = 1.0f / (1.0f + expf(-m));
    return (sg > 0.75f) & (n0 > 0.0f) & (n1 > 0.0f) & (n2 > 0.0f);
}

// ---------------------------------------------------------------------------
// Kernel A: fused zero-fill + min-reduction.
//   blocks [0, RB):       per-segment min of pc over valid pixels -> g_part
//   blocks [RB, RB+ZB):   zero the 512 MiB output grid (streaming stores)
// The reduction blocks (4 MB of reads) hide entirely under the zero-fill.
// ---------------------------------------------------------------------------
__global__ void fused_zero_reduce_k(const float* __restrict__ nocs,
                                    const float* __restrict__ ml,
                                    const float* __restrict__ trans,
                                    const float* __restrict__ scale,
                                    float4* __restrict__ out) {
    if (blockIdx.x >= RB) {
        // ------------- zero-fill path -------------
        int zb = blockIdx.x - RB;
        float4* p = out + (size_t)zb * F4_PER_BLK + threadIdx.x;
        const float4 z = make_float4(0.f, 0.f, 0.f, 0.f);
        #pragma unroll
        for (int i = 0; i < F4_PER_BLK / 256; i++)
            __stcs(p + i * 256, z);
        return;
    }

    // ------------- reduction path -------------
    int rb  = blockIdx.x;
    int b   = rb >> 3;
    int seg = rb & 7;
    int base = b * HW + seg * SEG_PIX;           // multiple of 4 -> float4 ok

    const float4* m4 = (const float4*)(ml   + base);
    const float4* x4 = (const float4*)(nocs + (b * 3 + 0) * HW + seg * SEG_PIX);
    const float4* y4 = (const float4*)(nocs + (b * 3 + 1) * HW + seg * SEG_PIX);
    const float4* z4 = (const float4*)(nocs + (b * 3 + 2) * HW + seg * SEG_PIX);

    float t0 = trans[b * 3 + 0], t1 = trans[b * 3 + 1], t2 = trans[b * 3 + 2];
    float s  = scale[b];

    float v0 = 1e10f, v1 = 1e10f, v2 = 1e10f;
    #pragma unroll
    for (int i = 0; i < SEG_PIX / 4 / 256; i++) {   // 8 iterations
        int j = threadIdx.x + i * 256;
        float4 m = m4[j], a = x4[j], c = y4[j], d = z4[j];
        const float* mp = &m.x; const float* ap = &a.x;
        const float* cp = &c.x; const float* dp = &d.x;
        #pragma unroll
        for (int k = 0; k < 4; k++) {
            if (valid_px(mp[k], ap[k], cp[k], dp[k])) {
                v0 = fminf(v0, pc_axis(ap[k], t0, s));
                v1 = fminf(v1, pc_axis(cp[k], t1, s));
                v2 = fminf(v2, pc_axis(dp[k], t2, s));
            }
        }
    }
    #pragma unroll
    for (int off = 16; off; off >>= 1) {
        v0 = fminf(v0, __shfl_down_sync(0xFFFFFFFFu, v0, off));
        v1 = fminf(v1, __shfl_down_sync(0xFFFFFFFFu, v1, off));
        v2 = fminf(v2, __shfl_down_sync(0xFFFFFFFFu, v2, off));
    }
    __shared__ float s0[8], s1[8], s2[8];
    int warp = threadIdx.x >> 5, lane = threadIdx.x & 31;
    if (lane == 0) { s0[warp] = v0; s1[warp] = v1; s2[warp] = v2; }
    __syncthreads();
    if (threadIdx.x == 0) {
        float m0 = s0[0], m1 = s1[0], m2 = s2[0];
        #pragma unroll
        for (int i = 1; i < 8; i++) {
            m0 = fminf(m0, s0[i]);
            m1 = fminf(m1, s1[i]);
            m2 = fminf(m2, s2[i]);
        }
        g_part[rb * 3 + 0] = m0;
        g_part[rb * 3 + 1] = m1;
        g_part[rb * 3 + 2] = m2;
    }
}

// ---------------------------------------------------------------------------
// Kernel B: scatter-add, parallelized over (pixel, channel-quad).
// Each thread owns ONE pixel and FOUR channels (cg = gid & 3 selects channels
// cg*4 .. cg*4+3). 4 threads share a pixel; their scalar input loads dedup in
// L1/L2. Same total RED count as before, but spread over 16x more blocks than
// R5 -> latency hiding. Index math: vox >= 0 (pc >= per-axis min) and the
// composed idx < 2^24, so int compose == reference float compose exactly.
// ---------------------------------------------------------------------------
__global__ void scatter_k(const float* __restrict__ nocs,
                          const float* __restrict__ ml,
                          const float* __restrict__ feat,
                          const float* __restrict__ trans,
                          const float* __restrict__ scale,
                          float* __restrict__ out) {
    int gid = blockIdx.x * blockDim.x + threadIdx.x;   // 0 .. 4*B*HW
    int pg  = gid >> 2;                                // pixel index 0..B*HW
    int cg  = gid & 3;                                 // channel quad 0..3
    int b   = pg >> 16;                                // pg / HW
    int pix = pg & (HW - 1);

    // 64 distinct pixels per block, all within one batch (HW % 64 == 0).
    __shared__ float lower[3];
    if (threadIdx.x < 3) {
        float m = 1e10f;
        #pragma unroll
        for (int j = 0; j < 8; j++)
            m = fminf(m, g_part[(b * 8 + j) * 3 + threadIdx.x]);
        lower[threadIdx.x] = m;
    }
    __syncthreads();

    float mlv = __ldg(ml   + b * HW + pix);
    float n0  = __ldg(nocs + (b * 3 + 0) * HW + pix);
    float n1  = __ldg(nocs + (b * 3 + 1) * HW + pix);
    float n2  = __ldg(nocs + (b * 3 + 2) * HW + pix);

    if (!valid_px(mlv, n0, n1, n2)) return;

    float s  = scale[b];
    float p0 = __fsub_rn(pc_axis(n0, trans[b * 3 + 0], s), lower[0]);
    float p1 = __fsub_rn(pc_axis(n1, trans[b * 3 + 1], s), lower[1]);
    float p2 = __fsub_rn(pc_axis(n2, trans[b * 3 + 2], s), lower[2]);

    // *128 exact (power of two); floor exact.
    int vx = (int)floorf(__fmul_rn(p0, 128.0f));
    int vy = (int)floorf(__fmul_rn(p1, 128.0f));
    int vz = (int)floorf(__fmul_rn(p2, 128.0f));
    int idx = vx * (RESV * RESV) + vy * RESV + vz;
    idx = min(max(idx, 0), RES3 - 1);

    int h = pix >> 8;
    int w = pix & 255;
    // nearest upsample 32x32 -> 256x256: source cell = (h/8, w/8)
    const float* fb = feat + (size_t)b * CC * FHW
                           + (size_t)(cg * 4) * FHW + (h >> 3) * 32 + (w >> 3);
    float* ob = out + (size_t)b * CC * RES3 + (size_t)(cg * 4) * RES3 + idx;

    #pragma unroll
    for (int c = 0; c < 4; c++)
        atomicAdd(ob + (size_t)c * RES3, __ldg(fb + c * FHW));  // RED.global
}

// ---------------------------------------------------------------------------
// Launch: two kernels, default stream, graph-capturable.
// ---------------------------------------------------------------------------
extern "C" void kernel_launch(void* const* d_in, const int* in_sizes, int n_in,
                              void* d_out, int out_size) {
    const float* nocs  = (const float*)d_in[0];  // [4,3,256,256]
    const float* ml    = (const float*)d_in[1];  // [4,1,256,256]
    const float* feat  = (const float*)d_in[2];  // [4,16,32,32]
    const float* trans = (const float*)d_in[3];  // [4,3]
    const float* scale = (const float*)d_in[4];  // [4]
    float*       out   = (float*)d_out;          // [4,16,128,128,128]

    fused_zero_reduce_k<<<RB + ZB, 256>>>(nocs, ml, trans, scale, (float4*)out);
    scatter_k<<<(4 * BB * HW) / 256, 256>>>(nocs, ml, feat, trans, scale, out);
}